// round 8
// baseline (speedup 1.0000x reference)
#include <cuda_runtime.h>
#include <math.h>
#include <stdint.h>

#define BB 1024
#define NN 512
#define EE 256
#define HH 128
#define AA 32
#define KC 32
#define APAD 136
#define BPAD 132
#define WPAD 36

// ---------------- scratch (device globals) ----------------------------------
__device__ float g_u     [(size_t)BB * NN];
__device__ float g_d2    [(size_t)BB * HH];
__device__ float g_d2wa  [(size_t)BB * AA];
__device__ float g_c2base[(size_t)BB * HH];
__device__ float g_c2    [(size_t)BB * HH];
// weights stored PERMUTED: wwt at [e*HH + (h&7)*16 + (h>>3)], wa at [e*AA + (a&7)*4 + (a>>3)]
__device__ float g_wwt_hi[(size_t)EE * HH];
__device__ float g_wwt_lo[(size_t)EE * HH];
__device__ float g_wa_hi [(size_t)EE * AA];
__device__ float g_wa_lo [(size_t)EE * AA];

__device__ __forceinline__ uint32_t f2tf32(float x) {
    uint32_t r;
    asm("cvt.rna.tf32.f32 %0, %1;" : "=r"(r) : "f"(x));
    return r;
}

#define MMA_TF32(C, A, B0, B1)                                                  \
    asm volatile(                                                               \
        "mma.sync.aligned.m16n8k8.row.col.f32.tf32.tf32.f32 "                   \
        "{%0,%1,%2,%3}, {%4,%5,%6,%7}, {%8,%9}, {%0,%1,%2,%3};"                 \
        : "+f"((C)[0]), "+f"((C)[1]), "+f"((C)[2]), "+f"((C)[3])                \
        : "r"((A)[0]), "r"((A)[1]), "r"((A)[2]), "r"((A)[3]),                   \
          "r"(B0), "r"(B1))

#define CP16(dst32, src) \
    asm volatile("cp.async.ca.shared.global [%0], [%1], 16;" :: "r"(dst32), "l"(src))
#define CP_COMMIT() asm volatile("cp.async.commit_group;")
#define CP_WAIT1()  asm volatile("cp.async.wait_group 1;")
#define CP_WAIT0()  asm volatile("cp.async.wait_group 0;")

// ---------------- k_pre: fused prew (permuted store) + d2v ------------------
__global__ void k_pre(const float* __restrict__ W1, const float* __restrict__ Wa,
                      const float* __restrict__ Wwt, const float* __restrict__ dec,
                      const float* __restrict__ W2, const float* __restrict__ b1,
                      const float* __restrict__ b2, const float* __restrict__ ba,
                      const float* __restrict__ bwt) {
    __shared__ float row[HH], d2s[HH];
    int h = threadIdx.x;
    if (blockIdx.x < EE) {
        int e = blockIdx.x;
        row[h] = W1[e * HH + h];
        __syncthreads();
        float acc = 0.f;
#pragma unroll 8
        for (int k = 0; k < HH; k++) acc = fmaf(row[k], Wwt[k * HH + h], acc);
        float hif = __uint_as_float(f2tf32(acc));
        int pl = (h & 7) * 16 + (h >> 3);
        g_wwt_hi[e * HH + pl] = hif;
        g_wwt_lo[e * HH + pl] = __uint_as_float(f2tf32(acc - hif));
        if (h < AA) {
            float a2 = 0.f;
#pragma unroll 8
            for (int k = 0; k < HH; k++) a2 = fmaf(row[k], Wa[k * AA + h], a2);
            float ahif = __uint_as_float(f2tf32(a2));
            int pu = (h & 7) * 4 + (h >> 3);
            g_wa_hi[e * AA + pu] = ahif;
            g_wa_lo[e * AA + pu] = __uint_as_float(f2tf32(a2 - ahif));
        }
    } else {
        int b = blockIdx.x - EE;
        row[h] = dec[b * HH + h];
        __syncthreads();
        float acc = b1[h] + b2[h];
#pragma unroll 8
        for (int k = 0; k < HH; k++) acc = fmaf(row[k], W2[k * HH + h], acc);
        d2s[h] = acc;
        g_d2[b * HH + h] = acc;
        __syncthreads();
        float c2 = bwt[h];
#pragma unroll 8
        for (int k = 0; k < HH; k++) c2 = fmaf(d2s[k], Wwt[k * HH + h], c2);
        g_c2base[b * HH + h] = c2;
        if (h < AA) {
            float aw = ba[h];
#pragma unroll 8
            for (int k = 0; k < HH; k++) aw = fmaf(d2s[k], Wa[k * AA + h], aw);
            g_d2wa[b * AA + h] = aw;
        }
    }
}

// ---------------- k_u_mma: u = tanh(enc^T@W1Wa + d2Wa)@Va + bva -------------
__global__ void __launch_bounds__(256, 3)
k_u_mma(const float* __restrict__ enc, const float* __restrict__ Va,
        const float* __restrict__ bva) {
    extern __shared__ float sm[];
    float* AS  = sm;
    float* BHs = AS + 2 * KC * APAD;
    float* BLs = BHs + 2 * KC * WPAD;
    float* d2a = BLs + 2 * KC * WPAD;
    float* vas = d2a + AA;

    const int tid  = threadIdx.x;
    const int lane = tid & 31, w = tid >> 5;
    const int gid  = lane >> 2, tig = lane & 3;
    const int b    = blockIdx.y;
    const int n0   = blockIdx.x * 128;

    if (tid < AA) { d2a[tid] = g_d2wa[b * AA + tid]; vas[tid] = Va[tid]; }
    const float bva0 = bva[0];

    const float* Ab = enc + (size_t)b * EE * NN + n0;
    const int lk   = tid >> 3;
    const int lnq  = (tid & 7) * 16;
    const int colB = (tid & 7) * 4;

    const uint32_t as_base = (uint32_t)__cvta_generic_to_shared(AS);
    const uint32_t bh_base = (uint32_t)__cvta_generic_to_shared(BHs);
    const uint32_t bl_base = (uint32_t)__cvta_generic_to_shared(BLs);

#define U_ISSUE(KT, BUF)                                                         \
    do {                                                                         \
        const float* arow_ = Ab + (size_t)((KT) * KC + lk) * NN + lnq;           \
        uint32_t ad_ = as_base + ((BUF) * KC * APAD + lk * APAD + lnq) * 4;      \
        CP16(ad_ + 0,  arow_ + 0);  CP16(ad_ + 16, arow_ + 4);                   \
        CP16(ad_ + 32, arow_ + 8);  CP16(ad_ + 48, arow_ + 12);                  \
        CP16(bh_base + ((BUF) * KC * WPAD + lk * WPAD + colB) * 4,               \
             g_wa_hi + (size_t)((KT) * KC + lk) * AA + colB);                    \
        CP16(bl_base + ((BUF) * KC * WPAD + lk * WPAD + colB) * 4,               \
             g_wa_lo + (size_t)((KT) * KC + lk) * AA + colB);                    \
    } while (0)

    float c[4][4];
#pragma unroll
    for (int nt = 0; nt < 4; nt++)
#pragma unroll
        for (int q = 0; q < 4; q++) c[nt][q] = 0.f;

    U_ISSUE(0, 0);
    CP_COMMIT();
    int cur = 0;
    for (int kt = 0; kt < 8; kt++) {
        if (kt < 7) { U_ISSUE(kt + 1, cur ^ 1); CP_COMMIT(); CP_WAIT1(); }
        else        { CP_WAIT0(); }
        __syncthreads();

        const float* Ac = AS + cur * KC * APAD;
        const float* Bh = BHs + cur * KC * WPAD;
        const float* Bl = BLs + cur * KC * WPAD;
        const int m = w * 16 + gid;
#pragma unroll
        for (int k8 = 0; k8 < 4; k8++) {
            const int kk = k8 * 8 + tig;
            float x0 = Ac[kk * APAD + m];
            float x1 = Ac[kk * APAD + m + 8];
            float x2 = Ac[(kk + 4) * APAD + m];
            float x3 = Ac[(kk + 4) * APAD + m + 8];
            uint32_t ah[4], al[4];
            ah[0] = f2tf32(x0); al[0] = f2tf32(x0 - __uint_as_float(ah[0]));
            ah[1] = f2tf32(x1); al[1] = f2tf32(x1 - __uint_as_float(ah[1]));
            ah[2] = f2tf32(x2); al[2] = f2tf32(x2 - __uint_as_float(ah[2]));
            ah[3] = f2tf32(x3); al[3] = f2tf32(x3 - __uint_as_float(ah[3]));
            float4 bh0 = *(const float4*)(Bh + kk * WPAD + gid * 4);
            float4 bh1 = *(const float4*)(Bh + (kk + 4) * WPAD + gid * 4);
            float4 bl0 = *(const float4*)(Bl + kk * WPAD + gid * 4);
            float4 bl1 = *(const float4*)(Bl + (kk + 4) * WPAD + gid * 4);
            const float bh0a[4] = {bh0.x, bh0.y, bh0.z, bh0.w};
            const float bh1a[4] = {bh1.x, bh1.y, bh1.z, bh1.w};
            const float bl0a[4] = {bl0.x, bl0.y, bl0.z, bl0.w};
            const float bl1a[4] = {bl1.x, bl1.y, bl1.z, bl1.w};
            // term-major: 4 independent accumulators between same-acc reuses
#pragma unroll
            for (int nt = 0; nt < 4; nt++)
                MMA_TF32(c[nt], ah, __float_as_uint(bh0a[nt]), __float_as_uint(bh1a[nt]));
#pragma unroll
            for (int nt = 0; nt < 4; nt++)
                MMA_TF32(c[nt], al, __float_as_uint(bh0a[nt]), __float_as_uint(bh1a[nt]));
#pragma unroll
            for (int nt = 0; nt < 4; nt++)
                MMA_TF32(c[nt], ah, __float_as_uint(bl0a[nt]), __float_as_uint(bl1a[nt]));
        }
        __syncthreads();
        cur ^= 1;
    }
#undef U_ISSUE

    float s0 = 0.f, s1 = 0.f;
#pragma unroll
    for (int nt = 0; nt < 4; nt++)
#pragma unroll
        for (int q = 0; q < 2; q++) {
            int a = nt * 8 + 2 * tig + q;
            s0 = fmaf(tanhf(c[nt][q]     + d2a[a]), vas[a], s0);
            s1 = fmaf(tanhf(c[nt][2 + q] + d2a[a]), vas[a], s1);
        }
    s0 += __shfl_xor_sync(0xffffffffu, s0, 1);
    s0 += __shfl_xor_sync(0xffffffffu, s0, 2);
    s1 += __shfl_xor_sync(0xffffffffu, s1, 1);
    s1 += __shfl_xor_sync(0xffffffffu, s1, 2);
    if (tig == 0) {
        g_u[(size_t)b * NN + n0 + w * 16 + gid]     = s0 + bva0;
        g_u[(size_t)b * NN + n0 + w * 16 + gid + 8] = s1 + bva0;
    }
}

// ---------------- k_soft: softmax(u); e_c = a^T enc; c_t; c2 ----------------
__global__ void __launch_bounds__(256)
k_soft(const float* __restrict__ enc, const float* __restrict__ W1,
       const float* __restrict__ Wct, const float* __restrict__ bct) {
    __shared__ float us[NN];
    __shared__ float red[256];
    __shared__ float ec[EE];
    __shared__ float cts[HH];
    int b = blockIdx.x, tid = threadIdx.x;

    float u0 = g_u[(size_t)b * NN + tid];
    float u1 = g_u[(size_t)b * NN + 256 + tid];
    red[tid] = fmaxf(u0, u1);
    __syncthreads();
    for (int s = 128; s > 0; s >>= 1) {
        if (tid < s) red[tid] = fmaxf(red[tid], red[tid + s]);
        __syncthreads();
    }
    float mx = red[0];
    __syncthreads();
    float p0 = expf(u0 - mx), p1 = expf(u1 - mx);
    red[tid] = p0 + p1;
    __syncthreads();
    for (int s = 128; s > 0; s >>= 1) {
        if (tid < s) red[tid] += red[tid + s];
        __syncthreads();
    }
    float invZ = 1.f / red[0];
    us[tid] = p0 * invZ;
    us[tid + 256] = p1 * invZ;
    __syncthreads();

    int w = tid >> 5, lane = tid & 31;
    const float* eb = enc + (size_t)b * EE * NN;
    const float4* us4 = (const float4*)us;
    for (int e = w; e < EE; e += 8) {
        const float4* er4 = (const float4*)(eb + (size_t)e * NN);
        float s = 0.f;
#pragma unroll 2
        for (int i = lane; i < NN / 4; i += 32) {
            float4 v = er4[i];
            float4 a = us4[i];
            s = fmaf(v.x, a.x, s); s = fmaf(v.y, a.y, s);
            s = fmaf(v.z, a.z, s); s = fmaf(v.w, a.w, s);
        }
        s += __shfl_xor_sync(0xffffffffu, s, 16);
        s += __shfl_xor_sync(0xffffffffu, s, 8);
        s += __shfl_xor_sync(0xffffffffu, s, 4);
        s += __shfl_xor_sync(0xffffffffu, s, 2);
        s += __shfl_xor_sync(0xffffffffu, s, 1);
        if (lane == 0) ec[e] = s;
    }
    __syncthreads();

    if (tid < HH) {
        float acc = g_d2[b * HH + tid];
#pragma unroll 8
        for (int k = 0; k < EE; k++) acc = fmaf(ec[k], W1[k * HH + tid], acc);
        cts[tid] = acc;
    }
    __syncthreads();
    if (tid < HH) {
        float c2 = g_c2base[b * HH + tid] + bct[tid];
#pragma unroll 8
        for (int k = 0; k < HH; k++) c2 = fmaf(cts[k], Wct[k * HH + tid], c2);
        g_c2[b * HH + tid] = c2;
    }
}

// ---------------- k_logits_mma: logits = tanh(enc^T@W1Wwt + c2)@Vc + bvc ----
// grid (4, B), block 256 (8 warps = 2 m-groups x 4 h-groups).
// Warp tile 64n x 32h (mt=4, nt=4). Term-major MMA ordering.
__global__ void __launch_bounds__(256, 2)
k_logits_mma(const float* __restrict__ enc, const float* __restrict__ Vc,
             const float* __restrict__ bvc, float* __restrict__ out) {
    extern __shared__ float sm[];
    float* AS  = sm;                      // 2 * KC*APAD
    float* BHs = AS + 2 * KC * APAD;      // 2 * KC*BPAD (permuted)
    float* BLs = BHs + 2 * KC * BPAD;     // 2 * KC*BPAD
    float* c2s = BLs + 2 * KC * BPAD;     // 128
    float* vcs = c2s + HH;                // 128
    float* ep  = vcs + HH;                // 128 * 4

    const int tid  = threadIdx.x;
    const int lane = tid & 31, w = tid >> 5;
    const int gid  = lane >> 2, tig = lane & 3;
    const int wm   = w >> 2;              // 0..1  (64-row group)
    const int wh   = w & 3;               // 0..3  (32-h group)
    const int b    = blockIdx.y;
    const int n0   = blockIdx.x * 128;

    if (tid < HH) { c2s[tid] = g_c2[b * HH + tid]; vcs[tid] = Vc[tid]; }
    const float bvc0 = bvc[0];

    const float* Ab = enc + (size_t)b * EE * NN + n0;
    const int lk  = tid >> 3;
    const int lnq = (tid & 7) * 16;

    const uint32_t as_base = (uint32_t)__cvta_generic_to_shared(AS);
    const uint32_t bh_base = (uint32_t)__cvta_generic_to_shared(BHs);
    const uint32_t bl_base = (uint32_t)__cvta_generic_to_shared(BLs);

#define L_ISSUE(KT, BUF)                                                         \
    do {                                                                         \
        const float* arow_ = Ab + (size_t)((KT) * KC + lk) * NN + lnq;           \
        const float* bhr_  = g_wwt_hi + (size_t)((KT) * KC + lk) * HH + lnq;     \
        const float* blr_  = g_wwt_lo + (size_t)((KT) * KC + lk) * HH + lnq;     \
        uint32_t ao_ = as_base + ((BUF) * KC * APAD + lk * APAD + lnq) * 4;      \
        uint32_t bo_ = (uint32_t)((BUF) * KC * BPAD + lk * BPAD + lnq) * 4;      \
        CP16(ao_ + 0,  arow_ + 0);  CP16(ao_ + 16, arow_ + 4);                   \
        CP16(ao_ + 32, arow_ + 8);  CP16(ao_ + 48, arow_ + 12);                  \
        CP16(bh_base + bo_ + 0,  bhr_ + 0);  CP16(bh_base + bo_ + 16, bhr_ + 4); \
        CP16(bh_base + bo_ + 32, bhr_ + 8);  CP16(bh_base + bo_ + 48, bhr_ + 12);\
        CP16(bl_base + bo_ + 0,  blr_ + 0);  CP16(bl_base + bo_ + 16, blr_ + 4); \
        CP16(bl_base + bo_ + 32, blr_ + 8);  CP16(bl_base + bo_ + 48, blr_ + 12);\
    } while (0)

    float c[4][4][4];   // [mt][nt][frag]
#pragma unroll
    for (int mt = 0; mt < 4; mt++)
#pragma unroll
        for (int nt = 0; nt < 4; nt++)
#pragma unroll
            for (int q = 0; q < 4; q++) c[mt][nt][q] = 0.f;

    L_ISSUE(0, 0);
    CP_COMMIT();
    int cur = 0;
    for (int kt = 0; kt < 8; kt++) {
        if (kt < 7) { L_ISSUE(kt + 1, cur ^ 1); CP_COMMIT(); CP_WAIT1(); }
        else        { CP_WAIT0(); }
        __syncthreads();

        const float* Ac = AS + cur * KC * APAD;
        const float* Bh = BHs + cur * KC * BPAD;
        const float* Bl = BLs + cur * KC * BPAD;
#pragma unroll
        for (int k8 = 0; k8 < 4; k8++) {
            const int kk = k8 * 8 + tig;
            // B fragments for all nt via permuted float4 loads
            float4 bh0 = *(const float4*)(Bh + kk * BPAD + gid * 16 + wh * 4);
            float4 bh1 = *(const float4*)(Bh + (kk + 4) * BPAD + gid * 16 + wh * 4);
            float4 bl0 = *(const float4*)(Bl + kk * BPAD + gid * 16 + wh * 4);
            float4 bl1 = *(const float4*)(Bl + (kk + 4) * BPAD + gid * 16 + wh * 4);
            const float bh0a[4] = {bh0.x, bh0.y, bh0.z, bh0.w};
            const float bh1a[4] = {bh1.x, bh1.y, bh1.z, bh1.w};
            const float bl0a[4] = {bl0.x, bl0.y, bl0.z, bl0.w};
            const float bl1a[4] = {bl1.x, bl1.y, bl1.z, bl1.w};
#pragma unroll
            for (int mh = 0; mh < 2; mh++) {
                uint32_t ah[2][4], al[2][4];
#pragma unroll
                for (int mt2 = 0; mt2 < 2; mt2++) {
                    const int m = wm * 64 + mh * 32 + mt2 * 16 + gid;
                    float x0 = Ac[kk * APAD + m];
                    float x1 = Ac[kk * APAD + m + 8];
                    float x2 = Ac[(kk + 4) * APAD + m];
                    float x3 = Ac[(kk + 4) * APAD + m + 8];
                    ah[mt2][0] = f2tf32(x0); al[mt2][0] = f2tf32(x0 - __uint_as_float(ah[mt2][0]));
                    ah[mt2][1] = f2tf32(x1); al[mt2][1] = f2tf32(x1 - __uint_as_float(ah[mt2][1]));
                    ah[mt2][2] = f2tf32(x2); al[mt2][2] = f2tf32(x2 - __uint_as_float(ah[mt2][2]));
                    ah[mt2][3] = f2tf32(x3); al[mt2][3] = f2tf32(x3 - __uint_as_float(ah[mt2][3]));
                }
                // term-major: 8 independent accumulators between same-acc reuses
#pragma unroll
                for (int nt = 0; nt < 4; nt++)
#pragma unroll
                    for (int mt2 = 0; mt2 < 2; mt2++)
                        MMA_TF32(c[mh * 2 + mt2][nt], ah[mt2],
                                 __float_as_uint(bh0a[nt]), __float_as_uint(bh1a[nt]));
#pragma unroll
                for (int nt = 0; nt < 4; nt++)
#pragma unroll
                    for (int mt2 = 0; mt2 < 2; mt2++)
                        MMA_TF32(c[mh * 2 + mt2][nt], al[mt2],
                                 __float_as_uint(bh0a[nt]), __float_as_uint(bh1a[nt]));
#pragma unroll
                for (int nt = 0; nt < 4; nt++)
#pragma unroll
                    for (int mt2 = 0; mt2 < 2; mt2++)
                        MMA_TF32(c[mh * 2 + mt2][nt], ah[mt2],
                                 __float_as_uint(bl0a[nt]), __float_as_uint(bl1a[nt]));
            }
        }
        __syncthreads();
        cur ^= 1;
    }
#undef L_ISSUE

    // epilogue: tanh + dot Vc over this warp's 32 h; shfl over tig, then
    // cross-warp (4 wh groups) reduce via ep.
#pragma unroll
    for (int mt = 0; mt < 4; mt++) {
        float s0 = 0.f, s1 = 0.f;
#pragma unroll
        for (int nt = 0; nt < 4; nt++)
#pragma unroll
            for (int q = 0; q < 2; q++) {
                int h = wh * 32 + nt * 8 + 2 * tig + q;
                s0 = fmaf(tanhf(c[mt][nt][q]     + c2s[h]), vcs[h], s0);
                s1 = fmaf(tanhf(c[mt][nt][2 + q] + c2s[h]), vcs[h], s1);
            }
        s0 += __shfl_xor_sync(0xffffffffu, s0, 1);
        s0 += __shfl_xor_sync(0xffffffffu, s0, 2);
        s1 += __shfl_xor_sync(0xffffffffu, s1, 1);
        s1 += __shfl_xor_sync(0xffffffffu, s1, 2);
        if (tig == 0) {
            int r = wm * 64 + mt * 16 + gid;
            ep[r * 4 + wh]       = s0;
            ep[(r + 8) * 4 + wh] = s1;
        }
    }
    __syncthreads();
    if (tid < 128)
        out[(size_t)b * NN + n0 + tid] =
            ep[tid * 4] + ep[tid * 4 + 1] + ep[tid * 4 + 2] + ep[tid * 4 + 3] + bvc0;
}

// ---------------- k_final: log_softmax, mask, argmax, outputs ---------------
__global__ void k_final(const float* __restrict__ demand, const float* __restrict__ load,
                        const void* __restrict__ veh_cap_raw, float* __restrict__ out) {
    __shared__ float sred[NN];
    __shared__ float sval[NN];
    __shared__ int   sidx[NN];
    __shared__ float s_ndsel;
    __shared__ int   s_ptr;
    int b = blockIdx.x, n = threadIdx.x;

    float logit = out[(size_t)b * NN + n];
    sred[n] = logit;
    __syncthreads();
    for (int s = 256; s > 0; s >>= 1) {
        if (n < s) sred[n] = fmaxf(sred[n], sred[n + s]);
        __syncthreads();
    }
    float mx = sred[0];
    __syncthreads();
    sred[n] = expf(logit - mx);
    __syncthreads();
    for (int s = 256; s > 0; s >>= 1) {
        if (n < s) sred[n] += sred[n + s];
        __syncthreads();
    }
    float lse = mx + logf(sred[0]);

    float dm = demand[(size_t)b * NN + n];
    float ld = load[b];
    float lp = logit - lse;
    if (n > 0 && (dm == 0.f || ld == 0.f)) lp = __int_as_float(0xff800000);
    out[(size_t)b * NN + n] = lp;

    sval[n] = lp; sidx[n] = n;
    __syncthreads();
    for (int s = 256; s > 0; s >>= 1) {
        if (n < s) {
            float v2 = sval[n + s]; int i2 = sidx[n + s];
            if (v2 > sval[n] || (v2 == sval[n] && i2 < sidx[n])) { sval[n] = v2; sidx[n] = i2; }
        }
        __syncthreads();
    }
    if (n == 0) {
        int ptr = sidx[0];
        float dsel = demand[(size_t)b * NN + ptr];
        float capf = *(const float*)veh_cap_raw;
        int   capi = *(const int*)veh_cap_raw;
        float cap = (capf > 0.5f && capf < 1.0e6f) ? capf : (float)capi;
        bool depot = (ptr == 0);
        float nload = depot ? cap : (ld - dsel);
        float ndsel = depot ? dsel : (dsel - nload);
        out[(size_t)BB * NN + b]      = (float)ptr;
        out[(size_t)BB * NN + BB + b] = nload;
        s_ptr = ptr; s_ndsel = ndsel;
    }
    __syncthreads();
    float ndv = (n == s_ptr) ? s_ndsel : dm;
    out[(size_t)BB * NN + 2 * (size_t)BB + (size_t)b * NN + n] = ndv;
}

// ---------------- launch ----------------------------------------------------
extern "C" void kernel_launch(void* const* d_in, const int* in_sizes, int n_in,
                              void* d_out, int out_size) {
    const float* dec  = (const float*)d_in[0];
    const float* enc  = (const float*)d_in[1];
    const float* load = (const float*)d_in[2];
    const float* dem  = (const float*)d_in[3];
    const float* W1   = (const float*)d_in[4];
    const float* b1   = (const float*)d_in[5];
    const float* W2   = (const float*)d_in[6];
    const float* b2   = (const float*)d_in[7];
    const float* Wwt  = (const float*)d_in[8];
    const float* bwt  = (const float*)d_in[9];
    const float* Wct  = (const float*)d_in[10];
    const float* bct  = (const float*)d_in[11];
    const float* Wa   = (const float*)d_in[12];
    const float* ba   = (const float*)d_in[13];
    const float* Va   = (const float*)d_in[14];
    const float* bva  = (const float*)d_in[15];
    const float* Vc   = (const float*)d_in[16];
    const float* bvc  = (const float*)d_in[17];
    const void*  vcap = (const void*)d_in[18];
    float* out = (float*)d_out;

    const int SMEM_U = (2 * KC * APAD + 4 * KC * WPAD + 2 * AA) * 4;            // 53504
    const int SMEM_L = (2 * KC * APAD + 4 * KC * BPAD + 2 * HH + 4 * HH) * 4;   // 105472
    static int attr_done = 0;
    if (!attr_done) {
        cudaFuncSetAttribute(k_u_mma, cudaFuncAttributeMaxDynamicSharedMemorySize, SMEM_U);
        cudaFuncSetAttribute(k_logits_mma, cudaFuncAttributeMaxDynamicSharedMemorySize, SMEM_L);
        attr_done = 1;
    }

    k_pre<<<EE + BB, HH>>>(W1, Wa, Wwt, dec, W2, b1, b2, ba, bwt);
    k_u_mma<<<dim3(4, BB), 256, SMEM_U>>>(enc, Va, bva);
    k_soft<<<BB, 256>>>(enc, W1, Wct, bct);
    k_logits_mma<<<dim3(4, BB), 256, SMEM_L>>>(enc, Vc, bvc, out);
    k_final<<<BB, NN>>>(dem, load, vcap, out);
}

// round 9
// speedup vs baseline: 1.7410x; 1.7410x over previous
#include <cuda_runtime.h>
#include <math.h>
#include <stdint.h>

#define BB 1024
#define NN 512
#define EE 256
#define HH 128
#define AA 32
#define KC 32
#define PADA 136   // packed-A smem row pad (u32)
#define PADB 132   // packed-B logits pad
#define PADW 40    // packed-B u pad
#define STGS 20    // staging slot stride (u32) per thread

// ---------------- scratch (device globals) ----------------------------------
__device__ float g_u     [(size_t)BB * NN];
__device__ float g_d2    [(size_t)BB * HH];
__device__ float g_d2wa  [(size_t)BB * AA];
__device__ float g_c2base[(size_t)BB * HH];
__device__ float g_c2    [(size_t)BB * HH];
// packed bf16x2 weights: pair over e (even in low half), h/a permuted:
//   wwt at [kp*HH + (h&7)*16 + (h>>3)],  wa at [kp*AA + (a&7)*4 + (a>>3)]
__device__ uint32_t g_wwtp_hi[(size_t)(EE / 2) * HH];
__device__ uint32_t g_wwtp_lo[(size_t)(EE / 2) * HH];
__device__ uint32_t g_wap_hi [(size_t)(EE / 2) * AA];
__device__ uint32_t g_wap_lo [(size_t)(EE / 2) * AA];

// split x0,x1 into bf16 hi pair + bf16 residual pair (x0 -> low half)
__device__ __forceinline__ void split_pack(float x0, float x1,
                                           uint32_t& ph, uint32_t& pl) {
    uint32_t h;
    asm("cvt.rn.bf16x2.f32 %0, %1, %2;" : "=r"(h) : "f"(x1), "f"(x0));
    float h0 = __uint_as_float(h << 16);
    float h1 = __uint_as_float(h & 0xffff0000u);
    asm("cvt.rn.bf16x2.f32 %0, %1, %2;" : "=r"(pl) : "f"(x1 - h1), "f"(x0 - h0));
    ph = h;
}

#define MMA_BF16(C, A, B0, B1)                                                  \
    asm volatile(                                                               \
        "mma.sync.aligned.m16n8k16.row.col.f32.bf16.bf16.f32 "                  \
        "{%0,%1,%2,%3}, {%4,%5,%6,%7}, {%8,%9}, {%0,%1,%2,%3};"                 \
        : "+f"((C)[0]), "+f"((C)[1]), "+f"((C)[2]), "+f"((C)[3])                \
        : "r"((A)[0]), "r"((A)[1]), "r"((A)[2]), "r"((A)[3]),                   \
          "r"(B0), "r"(B1))

#define CP16(dst32, src) \
    asm volatile("cp.async.ca.shared.global [%0], [%1], 16;" :: "r"(dst32), "l"(src))
#define CP8(dst32, src) \
    asm volatile("cp.async.ca.shared.global [%0], [%1], 8;" :: "r"(dst32), "l"(src))
#define CP_COMMIT() asm volatile("cp.async.commit_group;")
#define CP_WAIT0()  asm volatile("cp.async.wait_group 0;")

// ---------------- k_pre: packed weights (bid < EE/2) + d2v ------------------
__global__ void k_pre(const float* __restrict__ W1, const float* __restrict__ Wa,
                      const float* __restrict__ Wwt, const float* __restrict__ dec,
                      const float* __restrict__ W2, const float* __restrict__ b1,
                      const float* __restrict__ b2, const float* __restrict__ ba,
                      const float* __restrict__ bwt) {
    __shared__ float row0[HH], row1[HH];
    int h = threadIdx.x;
    if (blockIdx.x < EE / 2) {
        int e0 = blockIdx.x * 2;
        row0[h] = W1[e0 * HH + h];
        row1[h] = W1[(e0 + 1) * HH + h];
        __syncthreads();
        float a0 = 0.f, a1 = 0.f;
#pragma unroll 8
        for (int k = 0; k < HH; k++) {
            float wv = Wwt[k * HH + h];
            a0 = fmaf(row0[k], wv, a0);
            a1 = fmaf(row1[k], wv, a1);
        }
        uint32_t ph, pl;
        split_pack(a0, a1, ph, pl);
        int perm = (h & 7) * 16 + (h >> 3);
        g_wwtp_hi[blockIdx.x * HH + perm] = ph;
        g_wwtp_lo[blockIdx.x * HH + perm] = pl;
        if (h < AA) {
            float c0 = 0.f, c1 = 0.f;
#pragma unroll 8
            for (int k = 0; k < HH; k++) {
                float wv = Wa[k * AA + h];
                c0 = fmaf(row0[k], wv, c0);
                c1 = fmaf(row1[k], wv, c1);
            }
            uint32_t qh, ql;
            split_pack(c0, c1, qh, ql);
            int pa = (h & 7) * 4 + (h >> 3);
            g_wap_hi[blockIdx.x * AA + pa] = qh;
            g_wap_lo[blockIdx.x * AA + pa] = ql;
        }
    } else {
        int b = blockIdx.x - EE / 2;
        row0[h] = dec[b * HH + h];
        __syncthreads();
        float acc = b1[h] + b2[h];
#pragma unroll 8
        for (int k = 0; k < HH; k++) acc = fmaf(row0[k], W2[k * HH + h], acc);
        row1[h] = acc;
        g_d2[b * HH + h] = acc;
        __syncthreads();
        float c2 = bwt[h];
#pragma unroll 8
        for (int k = 0; k < HH; k++) c2 = fmaf(row1[k], Wwt[k * HH + h], c2);
        g_c2base[b * HH + h] = c2;
        if (h < AA) {
            float aw = ba[h];
#pragma unroll 8
            for (int k = 0; k < HH; k++) aw = fmaf(row1[k], Wa[k * AA + h], aw);
            g_d2wa[b * AA + h] = aw;
        }
    }
}

// shared A-stage + convert helpers -------------------------------------------
// staging: per-thread slot of STGS u32; thread (kp=tid>>4, n8=(tid&15)*8)
// owns rows 2kp,2kp+1 cols n8..n8+7 of the 32x128 tile.
__device__ __forceinline__ void stage_A(uint32_t stg_base, const float* Ab,
                                        int kt, int kp, int n8, int tid) {
    const float* r0 = Ab + (size_t)(kt * KC + 2 * kp) * NN + n8;
    const float* r1 = Ab + (size_t)(kt * KC + 2 * kp + 1) * NN + n8;
    uint32_t d = stg_base + (uint32_t)tid * STGS * 4;
    CP16(d + 0,  r0);     CP16(d + 16, r0 + 4);
    CP16(d + 32, r1);     CP16(d + 48, r1 + 4);
}

__device__ __forceinline__ void convert_A(const float* STG, uint32_t* AH,
                                          uint32_t* AL, int kp, int n8, int tid) {
    const float* s = STG + tid * STGS;
    float4 r0 = *(const float4*)(s + 0);
    float4 r1 = *(const float4*)(s + 4);
    float4 r2 = *(const float4*)(s + 8);
    float4 r3 = *(const float4*)(s + 12);
    uint32_t ph[8], pl[8];
    split_pack(r0.x, r2.x, ph[0], pl[0]); split_pack(r0.y, r2.y, ph[1], pl[1]);
    split_pack(r0.z, r2.z, ph[2], pl[2]); split_pack(r0.w, r2.w, ph[3], pl[3]);
    split_pack(r1.x, r3.x, ph[4], pl[4]); split_pack(r1.y, r3.y, ph[5], pl[5]);
    split_pack(r1.z, r3.z, ph[6], pl[6]); split_pack(r1.w, r3.w, ph[7], pl[7]);
    uint32_t* dh = AH + kp * PADA + n8;
    uint32_t* dl = AL + kp * PADA + n8;
    *(uint4*)(dh)     = make_uint4(ph[0], ph[1], ph[2], ph[3]);
    *(uint4*)(dh + 4) = make_uint4(ph[4], ph[5], ph[6], ph[7]);
    *(uint4*)(dl)     = make_uint4(pl[0], pl[1], pl[2], pl[3]);
    *(uint4*)(dl + 4) = make_uint4(pl[4], pl[5], pl[6], pl[7]);
}

// ---------------- k_u_mma: u = tanh(enc^T@W1Wa + d2Wa)@Va + bva -------------
__global__ void __launch_bounds__(256, 3)
k_u_mma(const float* __restrict__ enc, const float* __restrict__ Va,
        const float* __restrict__ bva) {
    extern __shared__ float smf[];
    float*    STG = smf;                              // 256*STGS
    uint32_t* AH  = (uint32_t*)(STG + 256 * STGS);    // 2*16*PADA
    uint32_t* AL  = AH + 2 * 16 * PADA;
    uint32_t* BH  = AL + 2 * 16 * PADA;               // 2*16*PADW
    uint32_t* BL  = BH + 2 * 16 * PADW;
    float*    d2a = (float*)(BL + 2 * 16 * PADW);     // 32
    float*    vas = d2a + AA;                         // 32

    const int tid  = threadIdx.x;
    const int lane = tid & 31, w = tid >> 5;
    const int gid  = lane >> 2, tig = lane & 3;
    const int b    = blockIdx.y;
    const int n0   = blockIdx.x * 128;

    if (tid < AA) { d2a[tid] = g_d2wa[b * AA + tid]; vas[tid] = Va[tid]; }
    const float bva0 = bva[0];

    const float* Ab = enc + (size_t)b * EE * NN + n0;
    const int kp = tid >> 4, n8 = (tid & 15) * 8;
    const int c2 = (tid & 15) * 2;
    const uint32_t stg_base = (uint32_t)__cvta_generic_to_shared(STG);
    const uint32_t bh_base  = (uint32_t)__cvta_generic_to_shared(BH);
    const uint32_t bl_base  = (uint32_t)__cvta_generic_to_shared(BL);

    float c[4][4];
#pragma unroll
    for (int nt = 0; nt < 4; nt++)
#pragma unroll
        for (int q = 0; q < 4; q++) c[nt][q] = 0.f;

    // prologue: group 0
    stage_A(stg_base, Ab, 0, kp, n8, tid);
    CP8(bh_base + (uint32_t)(kp * PADW + c2) * 4, g_wap_hi + kp * AA + c2);
    CP8(bl_base + (uint32_t)(kp * PADW + c2) * 4, g_wap_lo + kp * AA + c2);
    CP_COMMIT();

    int cur = 0;
    for (int kt = 0; kt < 8; kt++) {
        CP_WAIT0();
        __syncthreads();
        convert_A(STG, AH + cur * 16 * PADA, AL + cur * 16 * PADA, kp, n8, tid);
        __syncthreads();
        if (kt < 7) {
            stage_A(stg_base, Ab, kt + 1, kp, n8, tid);
            int nb = cur ^ 1;
            CP8(bh_base + (uint32_t)(nb * 16 * PADW + kp * PADW + c2) * 4,
                g_wap_hi + ((kt + 1) * 16 + kp) * AA + c2);
            CP8(bl_base + (uint32_t)(nb * 16 * PADW + kp * PADW + c2) * 4,
                g_wap_lo + ((kt + 1) * 16 + kp) * AA + c2);
            CP_COMMIT();
        }
        const uint32_t* Ah = AH + cur * 16 * PADA;
        const uint32_t* Al = AL + cur * 16 * PADA;
        const uint32_t* Bh = BH + cur * 16 * PADW;
        const uint32_t* Bl = BL + cur * 16 * PADW;
        const int m = w * 16 + gid;
#pragma unroll
        for (int ch = 0; ch < 2; ch++) {
            const int kpa = ch * 8 + tig;
            uint32_t ah[4], al[4];
            ah[0] = Ah[kpa * PADA + m];       ah[1] = Ah[kpa * PADA + m + 8];
            ah[2] = Ah[(kpa + 4) * PADA + m]; ah[3] = Ah[(kpa + 4) * PADA + m + 8];
            al[0] = Al[kpa * PADA + m];       al[1] = Al[kpa * PADA + m + 8];
            al[2] = Al[(kpa + 4) * PADA + m]; al[3] = Al[(kpa + 4) * PADA + m + 8];
            uint4 h0 = *(const uint4*)(Bh + kpa * PADW + gid * 4);
            uint4 h1 = *(const uint4*)(Bh + (kpa + 4) * PADW + gid * 4);
            uint4 l0 = *(const uint4*)(Bl + kpa * PADW + gid * 4);
            uint4 l1 = *(const uint4*)(Bl + (kpa + 4) * PADW + gid * 4);
            const uint32_t bh0[4] = {h0.x, h0.y, h0.z, h0.w};
            const uint32_t bh1[4] = {h1.x, h1.y, h1.z, h1.w};
            const uint32_t bl0[4] = {l0.x, l0.y, l0.z, l0.w};
            const uint32_t bl1[4] = {l1.x, l1.y, l1.z, l1.w};
#pragma unroll
            for (int nt = 0; nt < 4; nt++) MMA_BF16(c[nt], ah, bh0[nt], bh1[nt]);
#pragma unroll
            for (int nt = 0; nt < 4; nt++) MMA_BF16(c[nt], al, bh0[nt], bh1[nt]);
#pragma unroll
            for (int nt = 0; nt < 4; nt++) MMA_BF16(c[nt], ah, bl0[nt], bl1[nt]);
        }
        cur ^= 1;
    }

    float s0 = 0.f, s1 = 0.f;
#pragma unroll
    for (int nt = 0; nt < 4; nt++)
#pragma unroll
        for (int q = 0; q < 2; q++) {
            int a = nt * 8 + 2 * tig + q;
            s0 = fmaf(tanhf(c[nt][q]     + d2a[a]), vas[a], s0);
            s1 = fmaf(tanhf(c[nt][2 + q] + d2a[a]), vas[a], s1);
        }
    s0 += __shfl_xor_sync(0xffffffffu, s0, 1);
    s0 += __shfl_xor_sync(0xffffffffu, s0, 2);
    s1 += __shfl_xor_sync(0xffffffffu, s1, 1);
    s1 += __shfl_xor_sync(0xffffffffu, s1, 2);
    if (tig == 0) {
        g_u[(size_t)b * NN + n0 + w * 16 + gid]     = s0 + bva0;
        g_u[(size_t)b * NN + n0 + w * 16 + gid + 8] = s1 + bva0;
    }
}

// ---------------- k_soft: softmax(u); e_c = a^T enc; c_t; c2 ----------------
__global__ void __launch_bounds__(256)
k_soft(const float* __restrict__ enc, const float* __restrict__ W1,
       const float* __restrict__ Wct, const float* __restrict__ bct) {
    __shared__ float us[NN];
    __shared__ float red[256];
    __shared__ float ec[EE];
    __shared__ float cts[HH];
    int b = blockIdx.x, tid = threadIdx.x;

    float u0 = g_u[(size_t)b * NN + tid];
    float u1 = g_u[(size_t)b * NN + 256 + tid];
    red[tid] = fmaxf(u0, u1);
    __syncthreads();
    for (int s = 128; s > 0; s >>= 1) {
        if (tid < s) red[tid] = fmaxf(red[tid], red[tid + s]);
        __syncthreads();
    }
    float mx = red[0];
    __syncthreads();
    float p0 = expf(u0 - mx), p1 = expf(u1 - mx);
    red[tid] = p0 + p1;
    __syncthreads();
    for (int s = 128; s > 0; s >>= 1) {
        if (tid < s) red[tid] += red[tid + s];
        __syncthreads();
    }
    float invZ = 1.f / red[0];
    us[tid] = p0 * invZ;
    us[tid + 256] = p1 * invZ;
    __syncthreads();

    int w = tid >> 5, lane = tid & 31;
    const float* eb = enc + (size_t)b * EE * NN;
    const float4* us4 = (const float4*)us;
    for (int e = w; e < EE; e += 8) {
        const float4* er4 = (const float4*)(eb + (size_t)e * NN);
        float s = 0.f;
#pragma unroll 2
        for (int i = lane; i < NN / 4; i += 32) {
            float4 v = er4[i];
            float4 a = us4[i];
            s = fmaf(v.x, a.x, s); s = fmaf(v.y, a.y, s);
            s = fmaf(v.z, a.z, s); s = fmaf(v.w, a.w, s);
        }
        s += __shfl_xor_sync(0xffffffffu, s, 16);
        s += __shfl_xor_sync(0xffffffffu, s, 8);
        s += __shfl_xor_sync(0xffffffffu, s, 4);
        s += __shfl_xor_sync(0xffffffffu, s, 2);
        s += __shfl_xor_sync(0xffffffffu, s, 1);
        if (lane == 0) ec[e] = s;
    }
    __syncthreads();

    if (tid < HH) {
        float acc = g_d2[b * HH + tid];
#pragma unroll 8
        for (int k = 0; k < EE; k++) acc = fmaf(ec[k], W1[k * HH + tid], acc);
        cts[tid] = acc;
    }
    __syncthreads();
    if (tid < HH) {
        float c2 = g_c2base[b * HH + tid] + bct[tid];
#pragma unroll 8
        for (int k = 0; k < HH; k++) c2 = fmaf(cts[k], Wct[k * HH + tid], c2);
        g_c2[b * HH + tid] = c2;
    }
}

// ---------------- k_logits_mma: logits = tanh(enc^T@W1Wwt + c2)@Vc + bvc ----
// grid (4, B), block 256 (2 m-groups x 4 h-groups). Warp tile 64n x 32h.
__global__ void __launch_bounds__(256, 2)
k_logits_mma(const float* __restrict__ enc, const float* __restrict__ Vc,
             const float* __restrict__ bvc, float* __restrict__ out) {
    extern __shared__ float smf[];
    float*    STG = smf;                              // 256*STGS
    uint32_t* AH  = (uint32_t*)(STG + 256 * STGS);    // 2*16*PADA
    uint32_t* AL  = AH + 2 * 16 * PADA;
    uint32_t* BH  = AL + 2 * 16 * PADA;               // 2*16*PADB
    uint32_t* BL  = BH + 2 * 16 * PADB;
    float*    c2s = (float*)(BL + 2 * 16 * PADB);     // 128
    float*    vcs = c2s + HH;                         // 128
    float*    ep  = vcs + HH;                         // 512

    const int tid  = threadIdx.x;
    const int lane = tid & 31, w = tid >> 5;
    const int gid  = lane >> 2, tig = lane & 3;
    const int wm   = w >> 2;
    const int wh   = w & 3;
    const int b    = blockIdx.y;
    const int n0   = blockIdx.x * 128;

    if (tid < HH) { c2s[tid] = g_c2[b * HH + tid]; vcs[tid] = Vc[tid]; }
    const float bvc0 = bvc[0];

    const float* Ab = enc + (size_t)b * EE * NN + n0;
    const int kp = tid >> 4, n8 = (tid & 15) * 8;
    const int c8 = (tid & 15) * 8;
    const uint32_t stg_base = (uint32_t)__cvta_generic_to_shared(STG);
    const uint32_t bh_base  = (uint32_t)__cvta_generic_to_shared(BH);
    const uint32_t bl_base  = (uint32_t)__cvta_generic_to_shared(BL);

    float c[4][4][4];
#pragma unroll
    for (int mt = 0; mt < 4; mt++)
#pragma unroll
        for (int nt = 0; nt < 4; nt++)
#pragma unroll
            for (int q = 0; q < 4; q++) c[mt][nt][q] = 0.f;

    // prologue: group 0
    stage_A(stg_base, Ab, 0, kp, n8, tid);
    CP16(bh_base + (uint32_t)(kp * PADB + c8) * 4,       g_wwtp_hi + kp * HH + c8);
    CP16(bh_base + (uint32_t)(kp * PADB + c8 + 4) * 4,   g_wwtp_hi + kp * HH + c8 + 4);
    CP16(bl_base + (uint32_t)(kp * PADB + c8) * 4,       g_wwtp_lo + kp * HH + c8);
    CP16(bl_base + (uint32_t)(kp * PADB + c8 + 4) * 4,   g_wwtp_lo + kp * HH + c8 + 4);
    CP_COMMIT();

    int cur = 0;
    for (int kt = 0; kt < 8; kt++) {
        CP_WAIT0();
        __syncthreads();
        convert_A(STG, AH + cur * 16 * PADA, AL + cur * 16 * PADA, kp, n8, tid);
        __syncthreads();
        if (kt < 7) {
            stage_A(stg_base, Ab, kt + 1, kp, n8, tid);
            int nb = cur ^ 1;
            uint32_t bo = (uint32_t)(nb * 16 * PADB + kp * PADB + c8) * 4;
            const uint32_t* sh = g_wwtp_hi + ((kt + 1) * 16 + kp) * HH + c8;
            const uint32_t* sl = g_wwtp_lo + ((kt + 1) * 16 + kp) * HH + c8;
            CP16(bh_base + bo,      sh);  CP16(bh_base + bo + 16, sh + 4);
            CP16(bl_base + bo,      sl);  CP16(bl_base + bo + 16, sl + 4);
            CP_COMMIT();
        }
        const uint32_t* Ah = AH + cur * 16 * PADA;
        const uint32_t* Al = AL + cur * 16 * PADA;
        const uint32_t* Bh = BH + cur * 16 * PADB;
        const uint32_t* Bl = BL + cur * 16 * PADB;
#pragma unroll
        for (int ch = 0; ch < 2; ch++) {
            const int kpa = ch * 8 + tig;
            uint4 h0 = *(const uint4*)(Bh + kpa * PADB + gid * 16 + wh * 4);
            uint4 h1 = *(const uint4*)(Bh + (kpa + 4) * PADB + gid * 16 + wh * 4);
            uint4 l0 = *(const uint4*)(Bl + kpa * PADB + gid * 16 + wh * 4);
            uint4 l1 = *(const uint4*)(Bl + (kpa + 4) * PADB + gid * 16 + wh * 4);
            const uint32_t bh0[4] = {h0.x, h0.y, h0.z, h0.w};
            const uint32_t bh1[4] = {h1.x, h1.y, h1.z, h1.w};
            const uint32_t bl0[4] = {l0.x, l0.y, l0.z, l0.w};
            const uint32_t bl1[4] = {l1.x, l1.y, l1.z, l1.w};
#pragma unroll
            for (int mh = 0; mh < 2; mh++) {
                uint32_t ah[2][4], al[2][4];
#pragma unroll
                for (int mt2 = 0; mt2 < 2; mt2++) {
                    const int m = wm * 64 + mh * 32 + mt2 * 16 + gid;
                    ah[mt2][0] = Ah[kpa * PADA + m];
                    ah[mt2][1] = Ah[kpa * PADA + m + 8];
                    ah[mt2][2] = Ah[(kpa + 4) * PADA + m];
                    ah[mt2][3] = Ah[(kpa + 4) * PADA + m + 8];
                    al[mt2][0] = Al[kpa * PADA + m];
                    al[mt2][1] = Al[kpa * PADA + m + 8];
                    al[mt2][2] = Al[(kpa + 4) * PADA + m];
                    al[mt2][3] = Al[(kpa + 4) * PADA + m + 8];
                }
#pragma unroll
                for (int nt = 0; nt < 4; nt++)
#pragma unroll
                    for (int mt2 = 0; mt2 < 2; mt2++)
                        MMA_BF16(c[mh * 2 + mt2][nt], ah[mt2], bh0[nt], bh1[nt]);
#pragma unroll
                for (int nt = 0; nt < 4; nt++)
#pragma unroll
                    for (int mt2 = 0; mt2 < 2; mt2++)
                        MMA_BF16(c[mh * 2 + mt2][nt], al[mt2], bh0[nt], bh1[nt]);
#pragma unroll
                for (int nt = 0; nt < 4; nt++)
#pragma unroll
                    for (int mt2 = 0; mt2 < 2; mt2++)
                        MMA_BF16(c[mh * 2 + mt2][nt], ah[mt2], bl0[nt], bl1[nt]);
            }
        }
        cur ^= 1;
    }

    // epilogue: tanh + dot Vc over this warp's 32 h; shfl, then cross-warp ep
#pragma unroll
    for (int mt = 0; mt < 4; mt++) {
        float s0 = 0.f, s1 = 0.f;
#pragma unroll
        for (int nt = 0; nt < 4; nt++)
#pragma unroll
            for (int q = 0; q < 2; q++) {
                int h = wh * 32 + nt * 8 + 2 * tig + q;
                s0 = fmaf(tanhf(c[mt][nt][q]     + c2s[h]), vcs[h], s0);
                s1 = fmaf(tanhf(c[mt][nt][2 + q] + c2s[h]), vcs[h], s1);
            }
        s0 += __shfl_xor_sync(0xffffffffu, s0, 1);
        s0 += __shfl_xor_sync(0xffffffffu, s0, 2);
        s1 += __shfl_xor_sync(0xffffffffu, s1, 1);
        s1 += __shfl_xor_sync(0xffffffffu, s1, 2);
        if (tig == 0) {
            int r = wm * 64 + mt * 16 + gid;
            ep[r * 4 + wh]       = s0;
            ep[(r + 8) * 4 + wh] = s1;
        }
    }
    __syncthreads();
    if (tid < 128)
        out[(size_t)b * NN + n0 + tid] =
            ep[tid * 4] + ep[tid * 4 + 1] + ep[tid * 4 + 2] + ep[tid * 4 + 3] + bvc0;
}

// ---------------- k_final: log_softmax, mask, argmax, outputs ---------------
__global__ void k_final(const float* __restrict__ demand, const float* __restrict__ load,
                        const void* __restrict__ veh_cap_raw, float* __restrict__ out) {
    __shared__ float sred[NN];
    __shared__ float sval[NN];
    __shared__ int   sidx[NN];
    __shared__ float s_ndsel;
    __shared__ int   s_ptr;
    int b = blockIdx.x, n = threadIdx.x;

    float logit = out[(size_t)b * NN + n];
    sred[n] = logit;
    __syncthreads();
    for (int s = 256; s > 0; s >>= 1) {
        if (n < s) sred[n] = fmaxf(sred[n], sred[n + s]);
        __syncthreads();
    }
    float mx = sred[0];
    __syncthreads();
    sred[n] = expf(logit - mx);
    __syncthreads();
    for (int s = 256; s > 0; s >>= 1) {
        if (n < s) sred[n] += sred[n + s];
        __syncthreads();
    }
    float lse = mx + logf(sred[0]);

    float dm = demand[(size_t)b * NN + n];
    float ld = load[b];
    float lp = logit - lse;
    if (n > 0 && (dm == 0.f || ld == 0.f)) lp = __int_as_float(0xff800000);
    out[(size_t)b * NN + n] = lp;

    sval[n] = lp; sidx[n] = n;
    __syncthreads();
    for (int s = 256; s > 0; s >>= 1) {
        if (n < s) {
            float v2 = sval[n + s]; int i2 = sidx[n + s];
            if (v2 > sval[n] || (v2 == sval[n] && i2 < sidx[n])) { sval[n] = v2; sidx[n] = i2; }
        }
        __syncthreads();
    }
    if (n == 0) {
        int ptr = sidx[0];
        float dsel = demand[(size_t)b * NN + ptr];
        float capf = *(const float*)veh_cap_raw;
        int   capi = *(const int*)veh_cap_raw;
        float cap = (capf > 0.5f && capf < 1.0e6f) ? capf : (float)capi;
        bool depot = (ptr == 0);
        float nload = depot ? cap : (ld - dsel);
        float ndsel = depot ? dsel : (dsel - nload);
        out[(size_t)BB * NN + b]      = (float)ptr;
        out[(size_t)BB * NN + BB + b] = nload;
        s_ptr = ptr; s_ndsel = ndsel;
    }
    __syncthreads();
    float ndv = (n == s_ptr) ? s_ndsel : dm;
    out[(size_t)BB * NN + 2 * (size_t)BB + (size_t)b * NN + n] = ndv;
}

// ---------------- launch ----------------------------------------------------
extern "C" void kernel_launch(void* const* d_in, const int* in_sizes, int n_in,
                              void* d_out, int out_size) {
    const float* dec  = (const float*)d_in[0];
    const float* enc  = (const float*)d_in[1];
    const float* load = (const float*)d_in[2];
    const float* dem  = (const float*)d_in[3];
    const float* W1   = (const float*)d_in[4];
    const float* b1   = (const float*)d_in[5];
    const float* W2   = (const float*)d_in[6];
    const float* b2   = (const float*)d_in[7];
    const float* Wwt  = (const float*)d_in[8];
    const float* bwt  = (const float*)d_in[9];
    const float* Wct  = (const float*)d_in[10];
    const float* bct  = (const float*)d_in[11];
    const float* Wa   = (const float*)d_in[12];
    const float* ba   = (const float*)d_in[13];
    const float* Va   = (const float*)d_in[14];
    const float* bva  = (const float*)d_in[15];
    const float* Vc   = (const float*)d_in[16];
    const float* bvc  = (const float*)d_in[17];
    const void*  vcap = (const void*)d_in[18];
    float* out = (float*)d_out;

    const int SMEM_U = (256 * STGS + 4 * 16 * PADA + 4 * 16 * PADW + 2 * AA) * 4;
    const int SMEM_L = (256 * STGS + 4 * 16 * PADA + 4 * 16 * PADB + 2 * HH + 512) * 4;
    static int attr_done = 0;
    if (!attr_done) {
        cudaFuncSetAttribute(k_u_mma, cudaFuncAttributeMaxDynamicSharedMemorySize, SMEM_U);
        cudaFuncSetAttribute(k_logits_mma, cudaFuncAttributeMaxDynamicSharedMemorySize, SMEM_L);
        attr_done = 1;
    }

    k_pre<<<EE / 2 + BB, HH>>>(W1, Wa, Wwt, dec, W2, b1, b2, ba, bwt);
    k_u_mma<<<dim3(4, BB), 256, SMEM_U>>>(enc, Va, bva);
    k_soft<<<BB, 256>>>(enc, W1, Wct, bct);
    k_logits_mma<<<dim3(4, BB), 256, SMEM_L>>>(enc, Vc, bvc, out);
    k_final<<<BB, NN>>>(dem, load, vcap, out);
}